// round 13
// baseline (speedup 1.0000x reference)
#include <cuda_runtime.h>
#include <cuda_fp16.h>
#include <cstdint>

#define NN   50000
#define NE   800000
#define NREL 6
#define NL   8
#define DD   256
#define NG   512
#define KA   256          // GEMM K (single-pass fp16)
#define NC   1792         // 7*256 (6 rel + root)
#define BM   128
#define BNT  128
#define BK   32
#define MT   391          // ceil(50000/128)
#define NTM  14           // 1792/128
#define SCAT_BLKS  ((NE + 255) / 256)
#define CONVB_ELEMS ((size_t)NL * NC * KA)
#define CONVB_BLKS ((int)((CONVB_ELEMS + 255) / 256))
#define GP_ELEMS   (2 * 256 * 256)
#define GP_BLKS    (GP_ELEMS / 256)
#define POOLZ_BLKS ((NG * DD) / 256)

// ---------------- scratch ----------------
__device__ float   g_h   [(size_t)NN * DD];      //  51 MB fp32 hidden state
__device__ __half  g_xWh [(size_t)NN * NC];      // 179 MB fp16 transformed features
__device__ __half  g_Ah  [(size_t)NN * KA];      //  25.6 MB fp16 A (L2-resident)
__device__ __half  g_t1h [(size_t)NN * DD];      //  25.6 MB head intermediate
__device__ __half  g_B8  [CONVB_ELEMS];          //   7.3 MB fp16 all-layer weights
__device__ __half  g_Bgp [GP_ELEMS];             //  gp_W1 / gp_W2 fp16 (n-major)
__device__ int     g_deg [NN];
__device__ int     g_rowptr[NN + 1];
__device__ int     g_cursor[NN];
__device__ unsigned g_epack[NE];
__device__ float   g_pool[NG * DD];
__device__ float   g_z1  [NG * 1024];
__device__ float   g_z2  [NG * 512];

// ---------------- PTX helpers (baseline ISA only) ----------------
__device__ __forceinline__ uint32_t smem_u32(const void* p) {
    uint32_t a;
    asm("{ .reg .u64 t; cvta.to.shared.u64 t, %1; cvt.u32.u64 %0, t; }" : "=r"(a) : "l"(p));
    return a;
}
__device__ __forceinline__ void cp16(uint32_t s, const void* g) {
    asm volatile("cp.async.cg.shared.global [%0], [%1], 16;" :: "r"(s), "l"(g) : "memory");
}
__device__ __forceinline__ void cp_commit() {
    asm volatile("cp.async.commit_group;" ::: "memory");
}
template <int N>
__device__ __forceinline__ void cp_wait() {
    asm volatile("cp.async.wait_group %0;" :: "n"(N) : "memory");
}
__device__ __forceinline__ void ldsm4(uint32_t a, uint32_t* r) {
    asm volatile("ldmatrix.sync.aligned.m8n8.x4.shared.b16 {%0,%1,%2,%3}, [%4];"
                 : "=r"(r[0]), "=r"(r[1]), "=r"(r[2]), "=r"(r[3]) : "r"(a));
}
__device__ __forceinline__ void mma16816(float* c, const uint32_t* a, const uint32_t* b) {
    asm volatile(
        "mma.sync.aligned.m16n8k16.row.col.f32.f16.f16.f32 "
        "{%0,%1,%2,%3}, {%4,%5,%6,%7}, {%8,%9}, {%0,%1,%2,%3};"
        : "+f"(c[0]), "+f"(c[1]), "+f"(c[2]), "+f"(c[3])
        : "r"(a[0]), "r"(a[1]), "r"(a[2]), "r"(a[3]), "r"(b[0]), "r"(b[1]));
}
__device__ __forceinline__ int SW(int row, int cb) {
    return row * 64 + (cb ^ (((row >> 1) & 3) << 4));
}

// ---------------- encoder (+ zero deg, + layer-0 fp16 A) ----------------
__global__ void encoder_k(const float* __restrict__ x, const float* __restrict__ W,
                          const float* __restrict__ b) {
    int n = blockIdx.x;
    if (threadIdx.x == 0) g_deg[n] = 0;
    __shared__ float xr[13];
    if (threadIdx.x < 13) xr[threadIdx.x] = x[n * 13 + threadIdx.x];
    __syncthreads();
    int d = threadIdx.x;
    float s = b[d];
#pragma unroll
    for (int k = 0; k < 13; k++) s += xr[k] * W[k * DD + d];
    g_h[(size_t)n * DD + d] = s;
    g_Ah[(size_t)n * KA + d] = __float2half(s);
}

// ---------------- weight conversion (all layers + gp) + pool zero ----------------
__global__ void convB_k(const float* __restrict__ relW, const float* __restrict__ rootW,
                        const float* __restrict__ gpW1, const float* __restrict__ gpW2) {
    int b = blockIdx.x;
    if (b < CONVB_BLKS) {
        size_t idx = (size_t)b * 256 + threadIdx.x;
        if (idx >= CONVB_ELEMS) return;
        int l = (int)(idx / ((size_t)NC * KA));
        int r2 = (int)(idx % ((size_t)NC * KA));
        int n = r2 / KA, k = r2 - n * KA;
        float wv;
        if (n < 1536) {
            int r = n >> 8, c = n & 255;
            wv = relW[((((size_t)l * NREL + r) * DD + k) * DD) + c];
        } else {
            wv = rootW[(((size_t)l * DD + k) * DD) + (n - 1536)];
        }
        g_B8[idx] = __float2half(wv);
    } else if (b < CONVB_BLKS + GP_BLKS) {
        int idx = (b - CONVB_BLKS) * 256 + threadIdx.x;
        if (idx >= GP_ELEMS) return;
        int m = idx >> 16;           // 0: gpW1, 1: gpW2
        int r = idx & 65535;
        int n = r >> 8, k = r & 255; // B[n][k] = W[k][n]
        const float* W = m ? gpW2 : gpW1;
        g_Bgp[idx] = __float2half(W[k * 256 + n]);
    } else {
        int idx = (b - CONVB_BLKS - GP_BLKS) * 256 + threadIdx.x;
        if (idx < NG * DD) g_pool[idx] = 0.f;
    }
}

// ---------------- CSR: hist, coalesced scan, scatter ----------------
__global__ void hist_k(const int* __restrict__ ei) {
    int e = blockIdx.x * blockDim.x + threadIdx.x;
    if (e < NE) atomicAdd(&g_deg[ei[NE + e]], 1);
}
__global__ void scan_k() {
    __shared__ int wsum[32];
    __shared__ int s_run;
    int t = threadIdx.x, lane = t & 31, w = t >> 5;
    if (t == 0) s_run = 0;
    __syncthreads();
    for (int base = 0; base < NN; base += 1024) {
        int i = base + t;
        int v = (i < NN) ? g_deg[i] : 0;
        int xv = v;
#pragma unroll
        for (int o = 1; o < 32; o <<= 1) {
            int y = __shfl_up_sync(0xffffffffu, xv, o);
            if (lane >= o) xv += y;
        }
        if (lane == 31) wsum[w] = xv;
        __syncthreads();
        if (w == 0) {
            int z = wsum[lane];
#pragma unroll
            for (int o = 1; o < 32; o <<= 1) {
                int y = __shfl_up_sync(0xffffffffu, z, o);
                if (lane >= o) z += y;
            }
            wsum[lane] = z;
        }
        __syncthreads();
        int incl = xv + (w > 0 ? wsum[w - 1] : 0) + s_run;
        if (i < NN) { g_rowptr[i] = incl - v; g_cursor[i] = incl - v; }
        __syncthreads();
        if (t == 1023) s_run = incl;
        __syncthreads();
    }
    if (t == 0) g_rowptr[NN] = s_run;
}
__global__ void scatter_k(const int* __restrict__ ei, const int* __restrict__ et) {
    int e = blockIdx.x * blockDim.x + threadIdx.x;
    if (e >= NE) return;
    int dst = ei[NE + e];
    int pos = atomicAdd(&g_cursor[dst], 1);
    g_epack[pos] = (unsigned)ei[e] | ((unsigned)et[e] << 17);   // src:17 bits, type:3
}

// ---------------- fp16 mma.sync GEMM (3-stage, 1 sync/chunk): g_xWh = Ah @ B8[l]^T -----
__global__ __launch_bounds__(256, 2) void mma_k(int M, int layer) {
    __shared__ __align__(16) unsigned char sA[3][BM * 64];
    __shared__ __align__(16) unsigned char sB[3][BNT * 64];

    int tid = threadIdx.x, lane = tid & 31, wid = tid >> 5;
    int wm = (wid & 3) * 32;
    int wn = (wid >> 2) * 64;
    int bm0 = blockIdx.y * BM, bn0 = blockIdx.x * BNT;

    uint32_t aA[3] = {smem_u32(sA[0]), smem_u32(sA[1]), smem_u32(sA[2])};
    uint32_t aB[3] = {smem_u32(sB[0]), smem_u32(sB[1]), smem_u32(sB[2])};

    float acc[2][8][4];
#pragma unroll
    for (int i = 0; i < 2; i++)
#pragma unroll
        for (int j = 0; j < 8; j++)
#pragma unroll
            for (int q = 0; q < 4; q++) acc[i][j][q] = 0.f;

    const __half* A = g_Ah;
    const __half* B = g_B8 + (size_t)layer * NC * KA;

    auto load_stage = [&](int buf, int kc) {
#pragma unroll
        for (int i = 0; i < 2; i++) {
            int id = tid + i * 256;
            int row = id >> 2, cb = (id & 3) * 16;
            int gr = min(bm0 + row, M - 1);
            cp16(aA[buf] + SW(row, cb), A + (size_t)gr * KA + kc * BK + cb / 2);
        }
#pragma unroll
        for (int i = 0; i < 2; i++) {
            int id = tid + i * 256;
            int row = id >> 2, cb = (id & 3) * 16;
            cp16(aB[buf] + SW(row, cb), B + (size_t)(bn0 + row) * KA + kc * BK + cb / 2);
        }
        cp_commit();
    };

    const int NKC = KA / BK;  // 8
    load_stage(0, 0);
    load_stage(1, 1);

    for (int kc = 0; kc < NKC; kc++) {
        if (kc == NKC - 1) cp_wait<0>(); else cp_wait<1>();
        __syncthreads();   // stage kc ready AND all warps done with buf (kc+2)%3
        if (kc + 2 < NKC) load_stage((kc + 2) % 3, kc + 2);
        int buf = kc % 3;

#pragma unroll
        for (int kkx = 0; kkx < 2; kkx++) {
            uint32_t areg[2][4];
#pragma unroll
            for (int mt = 0; mt < 2; mt++) {
                int row = wm + mt * 16 + (lane & 15);
                int cb = kkx * 32 + ((lane >> 4) << 4);
                ldsm4(aA[buf] + SW(row, cb), areg[mt]);
            }
            uint32_t breg[8][2];
#pragma unroll
            for (int np = 0; np < 4; np++) {
                int row = wn + np * 16 + ((lane >> 4) << 3) + (lane & 7);
                int cb = kkx * 32 + (((lane >> 3) & 1) << 4);
                uint32_t r4[4];
                ldsm4(aB[buf] + SW(row, cb), r4);
                breg[np * 2 + 0][0] = r4[0]; breg[np * 2 + 0][1] = r4[1];
                breg[np * 2 + 1][0] = r4[2]; breg[np * 2 + 1][1] = r4[3];
            }
#pragma unroll
            for (int mt = 0; mt < 2; mt++)
#pragma unroll
                for (int nt = 0; nt < 8; nt++)
                    mma16816(acc[mt][nt], areg[mt], breg[nt]);
        }
    }

#pragma unroll
    for (int mt = 0; mt < 2; mt++) {
        int r0 = bm0 + wm + mt * 16 + (lane >> 2);
#pragma unroll
        for (int nt = 0; nt < 8; nt++) {
            int cn = bn0 + wn + nt * 8 + (lane & 3) * 2;
            if (r0 < M)
                *(__half2*)(g_xWh + (size_t)r0 * NC + cn) =
                    __floats2half2_rn(acc[mt][nt][0], acc[mt][nt][1]);
            if (r0 + 8 < M)
                *(__half2*)(g_xWh + (size_t)(r0 + 8) * NC + cn) =
                    __floats2half2_rn(acc[mt][nt][2], acc[mt][nt][3]);
        }
    }
}

// --------- fp16 head GEMM: (A @ B^T + bias)(relu?) -> dst fp16, or pooled atomics ------
__global__ __launch_bounds__(256, 2) void mma_head_k(const __half* __restrict__ A, int M,
                                                     const __half* __restrict__ B,
                                                     const float* __restrict__ bias, int relu,
                                                     __half* __restrict__ dst,
                                                     const int* __restrict__ pool_batch) {
    __shared__ __align__(16) unsigned char sA[3][BM * 64];
    __shared__ __align__(16) unsigned char sB[3][BNT * 64];

    int tid = threadIdx.x, lane = tid & 31, wid = tid >> 5;
    int wm = (wid & 3) * 32;
    int wn = (wid >> 2) * 64;
    int bm0 = blockIdx.y * BM, bn0 = blockIdx.x * BNT;

    uint32_t aA[3] = {smem_u32(sA[0]), smem_u32(sA[1]), smem_u32(sA[2])};
    uint32_t aB[3] = {smem_u32(sB[0]), smem_u32(sB[1]), smem_u32(sB[2])};

    float acc[2][8][4];
#pragma unroll
    for (int i = 0; i < 2; i++)
#pragma unroll
        for (int j = 0; j < 8; j++)
#pragma unroll
            for (int q = 0; q < 4; q++) acc[i][j][q] = 0.f;

    auto load_stage = [&](int buf, int kc) {
#pragma unroll
        for (int i = 0; i < 2; i++) {
            int id = tid + i * 256;
            int row = id >> 2, cb = (id & 3) * 16;
            int gr = min(bm0 + row, M - 1);
            cp16(aA[buf] + SW(row, cb), A + (size_t)gr * KA + kc * BK + cb / 2);
        }
#pragma unroll
        for (int i = 0; i < 2; i++) {
            int id = tid + i * 256;
            int row = id >> 2, cb = (id & 3) * 16;
            cp16(aB[buf] + SW(row, cb), B + (size_t)(bn0 + row) * KA + kc * BK + cb / 2);
        }
        cp_commit();
    };

    const int NKC = KA / BK;  // 8
    load_stage(0, 0);
    load_stage(1, 1);

    for (int kc = 0; kc < NKC; kc++) {
        if (kc == NKC - 1) cp_wait<0>(); else cp_wait<1>();
        __syncthreads();
        if (kc + 2 < NKC) load_stage((kc + 2) % 3, kc + 2);
        int buf = kc % 3;

#pragma unroll
        for (int kkx = 0; kkx < 2; kkx++) {
            uint32_t areg[2][4];
#pragma unroll
            for (int mt = 0; mt < 2; mt++) {
                int row = wm + mt * 16 + (lane & 15);
                int cb = kkx * 32 + ((lane >> 4) << 4);
                ldsm4(aA[buf] + SW(row, cb), areg[mt]);
            }
            uint32_t breg[8][2];
#pragma unroll
            for (int np = 0; np < 4; np++) {
                int row = wn + np * 16 + ((lane >> 4) << 3) + (lane & 7);
                int cb = kkx * 32 + (((lane >> 3) & 1) << 4);
                uint32_t r4[4];
                ldsm4(aB[buf] + SW(row, cb), r4);
                breg[np * 2 + 0][0] = r4[0]; breg[np * 2 + 0][1] = r4[1];
                breg[np * 2 + 1][0] = r4[2]; breg[np * 2 + 1][1] = r4[3];
            }
#pragma unroll
            for (int mt = 0; mt < 2; mt++)
#pragma unroll
                for (int nt = 0; nt < 8; nt++)
                    mma16816(acc[mt][nt], areg[mt], breg[nt]);
        }
    }

#pragma unroll
    for (int mt = 0; mt < 2; mt++) {
        int r0 = bm0 + wm + mt * 16 + (lane >> 2);
        int bg0 = 0, bg1 = 0;
        if (pool_batch) {
            if (r0 < M) bg0 = pool_batch[r0];
            if (r0 + 8 < M) bg1 = pool_batch[r0 + 8];
        }
#pragma unroll
        for (int nt = 0; nt < 8; nt++) {
            int cn = bn0 + wn + nt * 8 + (lane & 3) * 2;
            float b0 = bias[cn], b1 = bias[cn + 1];
            float v0 = acc[mt][nt][0] + b0, v1 = acc[mt][nt][1] + b1;
            float v2 = acc[mt][nt][2] + b0, v3 = acc[mt][nt][3] + b1;
            if (relu) {
                v0 = fmaxf(v0, 0.f); v1 = fmaxf(v1, 0.f);
                v2 = fmaxf(v2, 0.f); v3 = fmaxf(v3, 0.f);
            }
            if (pool_batch) {
                if (r0 < M) {
                    atomicAdd(g_pool + (size_t)bg0 * DD + cn, v0);
                    atomicAdd(g_pool + (size_t)bg0 * DD + cn + 1, v1);
                }
                if (r0 + 8 < M) {
                    atomicAdd(g_pool + (size_t)bg1 * DD + cn, v2);
                    atomicAdd(g_pool + (size_t)bg1 * DD + cn + 1, v3);
                }
            } else {
                if (r0 < M)
                    *(__half2*)(dst + (size_t)r0 * DD + cn) = __floats2half2_rn(v0, v1);
                if (r0 + 8 < M)
                    *(__half2*)(dst + (size_t)(r0 + 8) * DD + cn) = __floats2half2_rn(v2, v3);
            }
        }
    }
}

// ------- fused gather + root + skip + bias + PReLU + L2 norm + next-layer fp16 A -------
__global__ void gather_k(const float* __restrict__ convb, const float* __restrict__ pa) {
    int row = blockIdx.x;
    int t = threadIdx.x;   // 64 threads, 4 cols each
    const __half* xwr = g_xWh + (size_t)row * NC;
    uint2 rr = *(const uint2*)(xwr + 1536 + t * 4);                    // root
    float2 r0 = __half22float2(*(__half2*)&rr.x);
    float2 r1 = __half22float2(*(__half2*)&rr.y);
    float4 acc = make_float4(r0.x, r0.y, r1.x, r1.y);
    float4 h0  = *(const float4*)(g_h + (size_t)row * DD + t * 4);     // skip
    float4 cb  = *(const float4*)(convb + t * 4);
    acc.x += h0.x + cb.x; acc.y += h0.y + cb.y; acc.z += h0.z + cb.z; acc.w += h0.w + cb.w;
    int beg = g_rowptr[row], end = g_rowptr[row + 1];
    for (int i = beg; i < end; i++) {
        unsigned p = g_epack[i];
        int src = p & 0x1FFFF, typ = (p >> 17) & 7;
        uint2 mm = *(const uint2*)(g_xWh + (size_t)src * NC + typ * DD + t * 4);
        float2 m0 = __half22float2(*(__half2*)&mm.x);
        float2 m1 = __half22float2(*(__half2*)&mm.y);
        acc.x += m0.x; acc.y += m0.y; acc.z += m1.x; acc.w += m1.y;
    }
    float a = *pa;
    acc.x = acc.x > 0.f ? acc.x : a * acc.x;
    acc.y = acc.y > 0.f ? acc.y : a * acc.y;
    acc.z = acc.z > 0.f ? acc.z : a * acc.z;
    acc.w = acc.w > 0.f ? acc.w : a * acc.w;
    float s = acc.x * acc.x + acc.y * acc.y + acc.z * acc.z + acc.w * acc.w;
#pragma unroll
    for (int o = 16; o > 0; o >>= 1) s += __shfl_down_sync(0xffffffffu, s, o);
    __shared__ float sm[2];
    if ((t & 31) == 0) sm[t >> 5] = s;
    __syncthreads();
    float inv = 1.f / fmaxf(sqrtf(sm[0] + sm[1]), 1e-12f);
    acc.x *= inv; acc.y *= inv; acc.z *= inv; acc.w *= inv;
    *(float4*)(g_h + (size_t)row * DD + t * 4) = acc;
    __half* arow = g_Ah + (size_t)row * KA + t * 4;
    *(__half2*)(arow)     = __floats2half2_rn(acc.x, acc.y);
    *(__half2*)(arow + 2) = __floats2half2_rn(acc.z, acc.w);
}

// ---------------- fp32 SGEMM (fc head, small) ----------------
template <int BM_, int BN_, int BK_, int TM_, int TN_>
__global__ __launch_bounds__((BM_ / TM_) * (BN_ / TN_))
void sgemm_k(const float* __restrict__ A, const float* __restrict__ B,
             float* __restrict__ C, int M, int N, int K,
             const float* __restrict__ bias, int relu) {
    constexpr int NT = (BM_ / TM_) * (BN_ / TN_);
    __shared__ float As[BK_ * BM_];
    __shared__ float Bs[BK_ * BN_];
    int tid = threadIdx.x;
    int bm0 = blockIdx.y * BM_, bn0 = blockIdx.x * BN_;
    int tr = tid / (BN_ / TN_), tc = tid % (BN_ / TN_);
    float acc[TM_][TN_];
#pragma unroll
    for (int i = 0; i < TM_; i++)
#pragma unroll
        for (int j = 0; j < TN_; j++) acc[i][j] = 0.f;
    constexpr int AIT = (BM_ * BK_ / 4) / NT;
    constexpr int BIT = (BK_ * BN_ / 4) / NT;
    for (int k0 = 0; k0 < K; k0 += BK_) {
#pragma unroll
        for (int it = 0; it < AIT; it++) {
            int i = tid + it * NT;
            int ar = i / (BK_ / 4), ac = (i % (BK_ / 4)) * 4;
            float4 v = make_float4(0.f, 0.f, 0.f, 0.f);
            int gr = bm0 + ar;
            if (gr < M) v = *(const float4*)(A + (size_t)gr * K + k0 + ac);
            As[(ac + 0) * BM_ + ar] = v.x; As[(ac + 1) * BM_ + ar] = v.y;
            As[(ac + 2) * BM_ + ar] = v.z; As[(ac + 3) * BM_ + ar] = v.w;
        }
#pragma unroll
        for (int it = 0; it < BIT; it++) {
            int i = tid + it * NT;
            int br = i / (BN_ / 4), bc = (i % (BN_ / 4)) * 4;
            *(float4*)(Bs + br * BN_ + bc) = *(const float4*)(B + (size_t)(k0 + br) * N + bn0 + bc);
        }
        __syncthreads();
#pragma unroll
        for (int k = 0; k < BK_; k++) {
            float ra[TM_], rb[TN_];
#pragma unroll
            for (int i = 0; i < TM_; i++) ra[i] = As[k * BM_ + tr * TM_ + i];
#pragma unroll
            for (int j = 0; j < TN_; j++) rb[j] = Bs[k * BN_ + tc * TN_ + j];
#pragma unroll
            for (int i = 0; i < TM_; i++)
#pragma unroll
                for (int j = 0; j < TN_; j++) acc[i][j] += ra[i] * rb[j];
        }
        __syncthreads();
    }
#pragma unroll
    for (int i = 0; i < TM_; i++) {
        int row = bm0 + tr * TM_ + i;
        if (row >= M) continue;
#pragma unroll
        for (int j = 0; j < TN_; j += 4) {
            int col = bn0 + tc * TN_ + j;
            float4 v = make_float4(acc[i][j], acc[i][j + 1], acc[i][j + 2], acc[i][j + 3]);
            if (bias) {
                float4 bb = *(const float4*)(bias + col);
                v.x += bb.x; v.y += bb.y; v.z += bb.z; v.w += bb.w;
            }
            if (relu) {
                v.x = fmaxf(v.x, 0.f); v.y = fmaxf(v.y, 0.f);
                v.z = fmaxf(v.z, 0.f); v.w = fmaxf(v.w, 0.f);
            }
            *(float4*)(C + (size_t)row * N + col) = v;
        }
    }
}

// ---------------- output head ----------------
__global__ void out_k(const float* __restrict__ W, const float* __restrict__ b,
                      float* __restrict__ out) {
    int g = blockIdx.x;
    int t = threadIdx.x;
    float4 z = *(const float4*)(g_z2 + (size_t)g * 512 + t * 4);
    float4 w = *(const float4*)(W + t * 4);
    float s = z.x * w.x + z.y * w.y + z.z * w.z + z.w * w.w;
#pragma unroll
    for (int o = 16; o > 0; o >>= 1) s += __shfl_down_sync(0xffffffffu, s, o);
    __shared__ float sm[4];
    if ((t & 31) == 0) sm[t >> 5] = s;
    __syncthreads();
    if (t == 0) out[g] = fmaxf(sm[0] + sm[1] + sm[2] + sm[3] + b[0], 0.f);
}

// ---------------- launch ----------------
extern "C" void kernel_launch(void* const* d_in, const int* in_sizes, int n_in,
                              void* d_out, int out_size) {
    const float* x      = (const float*)d_in[0];
    const int*   ei     = (const int*)d_in[1];
    const int*   et     = (const int*)d_in[2];
    const int*   batch  = (const int*)d_in[3];
    const float* encW   = (const float*)d_in[4];
    const float* encb   = (const float*)d_in[5];
    const float* preluA = (const float*)d_in[6];
    const float* relW   = (const float*)d_in[7];
    const float* rootW  = (const float*)d_in[8];
    const float* convb  = (const float*)d_in[9];
    const float* gpW1   = (const float*)d_in[10];
    const float* gpb1   = (const float*)d_in[11];
    const float* gpW2   = (const float*)d_in[12];
    const float* gpb2   = (const float*)d_in[13];
    const float* fcW1   = (const float*)d_in[14];
    const float* fcb1   = (const float*)d_in[15];
    const float* fcW2   = (const float*)d_in[16];
    const float* fcb2   = (const float*)d_in[17];
    const float* outW   = (const float*)d_in[18];
    const float* outb   = (const float*)d_in[19];
    float*       out    = (float*)d_out;

    float *p_pool, *p_z1, *p_z2;
    __half *p_Ah, *p_t1h, *p_Bgp;
    cudaGetSymbolAddress((void**)&p_pool, g_pool);
    cudaGetSymbolAddress((void**)&p_z1, g_z1);
    cudaGetSymbolAddress((void**)&p_z2, g_z2);
    cudaGetSymbolAddress((void**)&p_Ah, g_Ah);
    cudaGetSymbolAddress((void**)&p_t1h, g_t1h);
    cudaGetSymbolAddress((void**)&p_Bgp, g_Bgp);

    // Ordered so mma_k is the 4th launch (ncu -s window catches it).
    encoder_k<<<NN, 256>>>(x, encW, encb);                                   // 1
    hist_k<<<(NE + 255) / 256, 256>>>(ei);                                   // 2
    convB_k<<<CONVB_BLKS + GP_BLKS + POOLZ_BLKS, 256>>>(relW, rootW, gpW1, gpW2); // 3
    mma_k<<<dim3(NTM, MT), 256>>>(NN, 0);                                    // 4 <- profile
    scan_k<<<1, 1024>>>();                                                   // 5
    scatter_k<<<(NE + 255) / 256, 256>>>(ei, et);                            // 6
    gather_k<<<NN, 64>>>(convb, preluA);                                     // 7 (layer 0)

    // layers 1..7
    for (int l = 1; l < NL; l++) {
        mma_k<<<dim3(NTM, MT), 256>>>(NN, l);
        gather_k<<<NN, 64>>>(convb + (size_t)l * DD, preluA);
    }

    // graph head (fp16 tensor path; head#2 pools directly)
    mma_head_k<<<dim3(2, MT), 256>>>(p_Ah, NN, p_Bgp, gpb1, 1, p_t1h, nullptr);
    mma_head_k<<<dim3(2, MT), 256>>>(p_t1h, NN, p_Bgp + 65536, gpb2, 0, nullptr, batch);

    sgemm_k<64, 64, 16, 4, 4><<<dim3(1024 / 64, NG / 64), 256>>>(
        p_pool, fcW1, p_z1, NG, 1024, DD, fcb1, 1);
    sgemm_k<64, 64, 16, 4, 4><<<dim3(512 / 64, NG / 64), 256>>>(
        p_z1, fcW2, p_z2, NG, 512, 1024, fcb2, 1);
    out_k<<<NG, 128>>>(outW, outb, out);
}

// round 14
// speedup vs baseline: 1.1720x; 1.1720x over previous
#include <cuda_runtime.h>
#include <cuda_fp16.h>
#include <cstdint>

#define NN   50000
#define NE   800000
#define NREL 6
#define NL   8
#define DD   256
#define NG   512
#define KA   256          // GEMM K (single-pass fp16)
#define NC   1792         // 7*256 (6 rel + root)
#define BM   128
#define BNT  128          // head GEMM N tile
#define BN2  256          // layer GEMM N tile (new 64x64 warp tiles)
#define BK   32
#define MT   391          // ceil(50000/128)
#define SCAT_BLKS  ((NE + 255) / 256)
#define CONVB_ELEMS ((size_t)NL * NC * KA)
#define CONVB_BLKS ((int)((CONVB_ELEMS + 255) / 256))
#define GP_ELEMS   (2 * 256 * 256)
#define GP_BLKS    (GP_ELEMS / 256)
#define POOLZ_BLKS ((NG * DD) / 256)

// ---------------- scratch ----------------
__device__ float   g_h   [(size_t)NN * DD];      //  51 MB fp32 hidden state
__device__ __half  g_xWh [(size_t)NN * NC];      // 179 MB fp16 transformed features
__device__ __half  g_Ah  [(size_t)NN * KA];      //  25.6 MB fp16 A (L2-resident)
__device__ __half  g_t1h [(size_t)NN * DD];      //  25.6 MB head intermediate
__device__ __half  g_gout[(size_t)NN * DD];      //  25.6 MB head output (pre-pool)
__device__ __half  g_B8  [CONVB_ELEMS];          //   7.3 MB fp16 all-layer weights
__device__ __half  g_Bgp [GP_ELEMS];             //  gp_W1 / gp_W2 fp16 (n-major)
__device__ int     g_deg [NN];
__device__ int     g_rowptr[NN + 1];
__device__ int     g_cursor[NN];
__device__ unsigned g_epack[NE];
__device__ float   g_pool[NG * DD];
__device__ float   g_z1  [NG * 1024];
__device__ float   g_z2  [NG * 512];

// ---------------- PTX helpers (baseline ISA only) ----------------
__device__ __forceinline__ uint32_t smem_u32(const void* p) {
    uint32_t a;
    asm("{ .reg .u64 t; cvta.to.shared.u64 t, %1; cvt.u32.u64 %0, t; }" : "=r"(a) : "l"(p));
    return a;
}
__device__ __forceinline__ void cp16(uint32_t s, const void* g) {
    asm volatile("cp.async.cg.shared.global [%0], [%1], 16;" :: "r"(s), "l"(g) : "memory");
}
__device__ __forceinline__ void cp_commit() {
    asm volatile("cp.async.commit_group;" ::: "memory");
}
template <int N>
__device__ __forceinline__ void cp_wait() {
    asm volatile("cp.async.wait_group %0;" :: "n"(N) : "memory");
}
__device__ __forceinline__ void ldsm4(uint32_t a, uint32_t* r) {
    asm volatile("ldmatrix.sync.aligned.m8n8.x4.shared.b16 {%0,%1,%2,%3}, [%4];"
                 : "=r"(r[0]), "=r"(r[1]), "=r"(r[2]), "=r"(r[3]) : "r"(a));
}
__device__ __forceinline__ void mma16816(float* c, const uint32_t* a, const uint32_t* b) {
    asm volatile(
        "mma.sync.aligned.m16n8k16.row.col.f32.f16.f16.f32 "
        "{%0,%1,%2,%3}, {%4,%5,%6,%7}, {%8,%9}, {%0,%1,%2,%3};"
        : "+f"(c[0]), "+f"(c[1]), "+f"(c[2]), "+f"(c[3])
        : "r"(a[0]), "r"(a[1]), "r"(a[2]), "r"(a[3]), "r"(b[0]), "r"(b[1]));
}
__device__ __forceinline__ int SW(int row, int cb) {
    return row * 64 + (cb ^ (((row >> 1) & 3) << 4));
}

// ---------------- encoder (+ zero deg, + layer-0 fp16 A) ----------------
__global__ void encoder_k(const float* __restrict__ x, const float* __restrict__ W,
                          const float* __restrict__ b) {
    int n = blockIdx.x;
    if (threadIdx.x == 0) g_deg[n] = 0;
    __shared__ float xr[13];
    if (threadIdx.x < 13) xr[threadIdx.x] = x[n * 13 + threadIdx.x];
    __syncthreads();
    int d = threadIdx.x;
    float s = b[d];
#pragma unroll
    for (int k = 0; k < 13; k++) s += xr[k] * W[k * DD + d];
    g_h[(size_t)n * DD + d] = s;
    g_Ah[(size_t)n * KA + d] = __float2half(s);
}

// ---------------- weight conversion (all layers + gp) + pool zero ----------------
__global__ void convB_k(const float* __restrict__ relW, const float* __restrict__ rootW,
                        const float* __restrict__ gpW1, const float* __restrict__ gpW2) {
    int b = blockIdx.x;
    if (b < CONVB_BLKS) {
        size_t idx = (size_t)b * 256 + threadIdx.x;
        if (idx >= CONVB_ELEMS) return;
        int l = (int)(idx / ((size_t)NC * KA));
        int r2 = (int)(idx % ((size_t)NC * KA));
        int n = r2 / KA, k = r2 - n * KA;
        float wv;
        if (n < 1536) {
            int r = n >> 8, c = n & 255;
            wv = relW[((((size_t)l * NREL + r) * DD + k) * DD) + c];
        } else {
            wv = rootW[(((size_t)l * DD + k) * DD) + (n - 1536)];
        }
        g_B8[idx] = __float2half(wv);
    } else if (b < CONVB_BLKS + GP_BLKS) {
        int idx = (b - CONVB_BLKS) * 256 + threadIdx.x;
        if (idx >= GP_ELEMS) return;
        int m = idx >> 16;           // 0: gpW1, 1: gpW2
        int r = idx & 65535;
        int n = r >> 8, k = r & 255; // B[n][k] = W[k][n]
        const float* W = m ? gpW2 : gpW1;
        g_Bgp[idx] = __float2half(W[k * 256 + n]);
    } else {
        int idx = (b - CONVB_BLKS - GP_BLKS) * 256 + threadIdx.x;
        if (idx < NG * DD) g_pool[idx] = 0.f;
    }
}

// ---------------- CSR: hist, coalesced scan, scatter ----------------
__global__ void hist_k(const int* __restrict__ ei) {
    int e = blockIdx.x * blockDim.x + threadIdx.x;
    if (e < NE) atomicAdd(&g_deg[ei[NE + e]], 1);
}
__global__ void scan_k() {
    __shared__ int wsum[32];
    __shared__ int s_run;
    int t = threadIdx.x, lane = t & 31, w = t >> 5;
    if (t == 0) s_run = 0;
    __syncthreads();
    for (int base = 0; base < NN; base += 1024) {
        int i = base + t;
        int v = (i < NN) ? g_deg[i] : 0;
        int xv = v;
#pragma unroll
        for (int o = 1; o < 32; o <<= 1) {
            int y = __shfl_up_sync(0xffffffffu, xv, o);
            if (lane >= o) xv += y;
        }
        if (lane == 31) wsum[w] = xv;
        __syncthreads();
        if (w == 0) {
            int z = wsum[lane];
#pragma unroll
            for (int o = 1; o < 32; o <<= 1) {
                int y = __shfl_up_sync(0xffffffffu, z, o);
                if (lane >= o) z += y;
            }
            wsum[lane] = z;
        }
        __syncthreads();
        int incl = xv + (w > 0 ? wsum[w - 1] : 0) + s_run;
        if (i < NN) { g_rowptr[i] = incl - v; g_cursor[i] = incl - v; }
        __syncthreads();
        if (t == 1023) s_run = incl;
        __syncthreads();
    }
    if (t == 0) g_rowptr[NN] = s_run;
}
__global__ void scatter_k(const int* __restrict__ ei, const int* __restrict__ et) {
    int e = blockIdx.x * blockDim.x + threadIdx.x;
    if (e >= NE) return;
    int dst = ei[NE + e];
    int pos = atomicAdd(&g_cursor[dst], 1);
    g_epack[pos] = (unsigned)ei[e] | ((unsigned)et[e] << 17);   // src:17 bits, type:3
}

// -------- fp16 mma GEMM, 64x64 warp tiles (block 128x256, 2-stage): g_xWh = Ah @ B8^T --
__global__ __launch_bounds__(256, 1) void mma_k(int M, int layer) {
    __shared__ __align__(16) unsigned char sA[2][BM * 64];    // 16 KB
    __shared__ __align__(16) unsigned char sB[2][BN2 * 64];   // 32 KB (48 KB total)

    int tid = threadIdx.x, lane = tid & 31, wid = tid >> 5;
    int wm = (wid & 1) * 64;          // 2 warps down (m)
    int wn = (wid >> 1) * 64;         // 4 warps across (n)
    int bm0 = blockIdx.y * BM, bn0 = blockIdx.x * BN2;

    uint32_t aA[2] = {smem_u32(sA[0]), smem_u32(sA[1])};
    uint32_t aB[2] = {smem_u32(sB[0]), smem_u32(sB[1])};

    float acc[4][8][4];
#pragma unroll
    for (int i = 0; i < 4; i++)
#pragma unroll
        for (int j = 0; j < 8; j++)
#pragma unroll
            for (int q = 0; q < 4; q++) acc[i][j][q] = 0.f;

    const __half* A = g_Ah;
    const __half* B = g_B8 + (size_t)layer * NC * KA;

    auto load_stage = [&](int buf, int kc) {
#pragma unroll
        for (int i = 0; i < 2; i++) {                       // A: 512 x 16B
            int id = tid + i * 256;
            int row = id >> 2, cb = (id & 3) * 16;
            int gr = min(bm0 + row, M - 1);
            cp16(aA[buf] + SW(row, cb), A + (size_t)gr * KA + kc * BK + cb / 2);
        }
#pragma unroll
        for (int i = 0; i < 4; i++) {                       // B: 1024 x 16B
            int id = tid + i * 256;
            int row = id >> 2, cb = (id & 3) * 16;
            cp16(aB[buf] + SW(row, cb), B + (size_t)(bn0 + row) * KA + kc * BK + cb / 2);
        }
        cp_commit();
    };

    const int NKC = KA / BK;  // 8
    load_stage(0, 0);

    for (int kc = 0; kc < NKC; kc++) {
        if (kc + 1 < NKC) { load_stage((kc + 1) & 1, kc + 1); cp_wait<1>(); }
        else cp_wait<0>();
        __syncthreads();
        int buf = kc & 1;

#pragma unroll
        for (int kkx = 0; kkx < 2; kkx++) {
            uint32_t areg[4][4];
#pragma unroll
            for (int mt = 0; mt < 4; mt++) {
                int row = wm + mt * 16 + (lane & 15);
                int cb = kkx * 32 + ((lane >> 4) << 4);
                ldsm4(aA[buf] + SW(row, cb), areg[mt]);
            }
            uint32_t breg[8][2];
#pragma unroll
            for (int np = 0; np < 4; np++) {
                int row = wn + np * 16 + ((lane >> 4) << 3) + (lane & 7);
                int cb = kkx * 32 + (((lane >> 3) & 1) << 4);
                uint32_t r4[4];
                ldsm4(aB[buf] + SW(row, cb), r4);
                breg[np * 2 + 0][0] = r4[0]; breg[np * 2 + 0][1] = r4[1];
                breg[np * 2 + 1][0] = r4[2]; breg[np * 2 + 1][1] = r4[3];
            }
#pragma unroll
            for (int mt = 0; mt < 4; mt++)
#pragma unroll
                for (int nt = 0; nt < 8; nt++)
                    mma16816(acc[mt][nt], areg[mt], breg[nt]);
        }
        __syncthreads();   // all warps done with buf before it is reloaded next iter
    }

#pragma unroll
    for (int mt = 0; mt < 4; mt++) {
        int r0 = bm0 + wm + mt * 16 + (lane >> 2);
#pragma unroll
        for (int nt = 0; nt < 8; nt++) {
            int cn = bn0 + wn + nt * 8 + (lane & 3) * 2;
            if (r0 < M)
                *(__half2*)(g_xWh + (size_t)r0 * NC + cn) =
                    __floats2half2_rn(acc[mt][nt][0], acc[mt][nt][1]);
            if (r0 + 8 < M)
                *(__half2*)(g_xWh + (size_t)(r0 + 8) * NC + cn) =
                    __floats2half2_rn(acc[mt][nt][2], acc[mt][nt][3]);
        }
    }
}

// ---------------- fp16 head GEMM (32x64 warp tiles, 3-stage): dst = A @ B^T ------------
__global__ __launch_bounds__(256, 2) void mma_head_k(const __half* __restrict__ A, int M,
                                                     const __half* __restrict__ B,
                                                     const float* __restrict__ bias, int relu,
                                                     __half* __restrict__ dst) {
    __shared__ __align__(16) unsigned char sA[3][BM * 64];
    __shared__ __align__(16) unsigned char sB[3][BNT * 64];

    int tid = threadIdx.x, lane = tid & 31, wid = tid >> 5;
    int wm = (wid & 3) * 32;
    int wn = (wid >> 2) * 64;
    int bm0 = blockIdx.y * BM, bn0 = blockIdx.x * BNT;

    uint32_t aA[3] = {smem_u32(sA[0]), smem_u32(sA[1]), smem_u32(sA[2])};
    uint32_t aB[3] = {smem_u32(sB[0]), smem_u32(sB[1]), smem_u32(sB[2])};

    float acc[2][8][4];
#pragma unroll
    for (int i = 0; i < 2; i++)
#pragma unroll
        for (int j = 0; j < 8; j++)
#pragma unroll
            for (int q = 0; q < 4; q++) acc[i][j][q] = 0.f;

    auto load_stage = [&](int buf, int kc) {
#pragma unroll
        for (int i = 0; i < 2; i++) {
            int id = tid + i * 256;
            int row = id >> 2, cb = (id & 3) * 16;
            int gr = min(bm0 + row, M - 1);
            cp16(aA[buf] + SW(row, cb), A + (size_t)gr * KA + kc * BK + cb / 2);
        }
#pragma unroll
        for (int i = 0; i < 2; i++) {
            int id = tid + i * 256;
            int row = id >> 2, cb = (id & 3) * 16;
            cp16(aB[buf] + SW(row, cb), B + (size_t)(bn0 + row) * KA + kc * BK + cb / 2);
        }
        cp_commit();
    };

    const int NKC = KA / BK;  // 8
    load_stage(0, 0);
    load_stage(1, 1);

    for (int kc = 0; kc < NKC; kc++) {
        if (kc == NKC - 1) cp_wait<0>(); else cp_wait<1>();
        __syncthreads();
        if (kc + 2 < NKC) load_stage((kc + 2) % 3, kc + 2);
        int buf = kc % 3;

#pragma unroll
        for (int kkx = 0; kkx < 2; kkx++) {
            uint32_t areg[2][4];
#pragma unroll
            for (int mt = 0; mt < 2; mt++) {
                int row = wm + mt * 16 + (lane & 15);
                int cb = kkx * 32 + ((lane >> 4) << 4);
                ldsm4(aA[buf] + SW(row, cb), areg[mt]);
            }
            uint32_t breg[8][2];
#pragma unroll
            for (int np = 0; np < 4; np++) {
                int row = wn + np * 16 + ((lane >> 4) << 3) + (lane & 7);
                int cb = kkx * 32 + (((lane >> 3) & 1) << 4);
                uint32_t r4[4];
                ldsm4(aB[buf] + SW(row, cb), r4);
                breg[np * 2 + 0][0] = r4[0]; breg[np * 2 + 0][1] = r4[1];
                breg[np * 2 + 1][0] = r4[2]; breg[np * 2 + 1][1] = r4[3];
            }
#pragma unroll
            for (int mt = 0; mt < 2; mt++)
#pragma unroll
                for (int nt = 0; nt < 8; nt++)
                    mma16816(acc[mt][nt], areg[mt], breg[nt]);
        }
    }

#pragma unroll
    for (int mt = 0; mt < 2; mt++) {
        int r0 = bm0 + wm + mt * 16 + (lane >> 2);
#pragma unroll
        for (int nt = 0; nt < 8; nt++) {
            int cn = bn0 + wn + nt * 8 + (lane & 3) * 2;
            float b0 = bias[cn], b1 = bias[cn + 1];
            float v0 = acc[mt][nt][0] + b0, v1 = acc[mt][nt][1] + b1;
            float v2 = acc[mt][nt][2] + b0, v3 = acc[mt][nt][3] + b1;
            if (relu) {
                v0 = fmaxf(v0, 0.f); v1 = fmaxf(v1, 0.f);
                v2 = fmaxf(v2, 0.f); v3 = fmaxf(v3, 0.f);
            }
            if (r0 < M)
                *(__half2*)(dst + (size_t)r0 * DD + cn) = __floats2half2_rn(v0, v1);
            if (r0 + 8 < M)
                *(__half2*)(dst + (size_t)(r0 + 8) * DD + cn) = __floats2half2_rn(v2, v3);
        }
    }
}

// ------- fused gather + root + skip + bias + PReLU + L2 norm + next-layer fp16 A -------
__global__ void gather_k(const float* __restrict__ convb, const float* __restrict__ pa) {
    int row = blockIdx.x;
    int t = threadIdx.x;   // 64 threads, 4 cols each
    const __half* xwr = g_xWh + (size_t)row * NC;
    uint2 rr = *(const uint2*)(xwr + 1536 + t * 4);                    // root
    float2 r0 = __half22float2(*(__half2*)&rr.x);
    float2 r1 = __half22float2(*(__half2*)&rr.y);
    float4 acc = make_float4(r0.x, r0.y, r1.x, r1.y);
    float4 h0  = *(const float4*)(g_h + (size_t)row * DD + t * 4);     // skip
    float4 cb  = *(const float4*)(convb + t * 4);
    acc.x += h0.x + cb.x; acc.y += h0.y + cb.y; acc.z += h0.z + cb.z; acc.w += h0.w + cb.w;
    int beg = g_rowptr[row], end = g_rowptr[row + 1];
    for (int i = beg; i < end; i++) {
        unsigned p = g_epack[i];
        int src = p & 0x1FFFF, typ = (p >> 17) & 7;
        uint2 mm = *(const uint2*)(g_xWh + (size_t)src * NC + typ * DD + t * 4);
        float2 m0 = __half22float2(*(__half2*)&mm.x);
        float2 m1 = __half22float2(*(__half2*)&mm.y);
        acc.x += m0.x; acc.y += m0.y; acc.z += m1.x; acc.w += m1.y;
    }
    float a = *pa;
    acc.x = acc.x > 0.f ? acc.x : a * acc.x;
    acc.y = acc.y > 0.f ? acc.y : a * acc.y;
    acc.z = acc.z > 0.f ? acc.z : a * acc.z;
    acc.w = acc.w > 0.f ? acc.w : a * acc.w;
    float s = acc.x * acc.x + acc.y * acc.y + acc.z * acc.z + acc.w * acc.w;
#pragma unroll
    for (int o = 16; o > 0; o >>= 1) s += __shfl_down_sync(0xffffffffu, s, o);
    __shared__ float sm[2];
    if ((t & 31) == 0) sm[t >> 5] = s;
    __syncthreads();
    float inv = 1.f / fmaxf(sqrtf(sm[0] + sm[1]), 1e-12f);
    acc.x *= inv; acc.y *= inv; acc.z *= inv; acc.w *= inv;
    *(float4*)(g_h + (size_t)row * DD + t * 4) = acc;
    __half* arow = g_Ah + (size_t)row * KA + t * 4;
    *(__half2*)(arow)     = __floats2half2_rn(acc.x, acc.y);
    *(__half2*)(arow + 2) = __floats2half2_rn(acc.z, acc.w);
}

// ---------------- fp32 SGEMM (fc head, small) ----------------
template <int BM_, int BN_, int BK_, int TM_, int TN_>
__global__ __launch_bounds__((BM_ / TM_) * (BN_ / TN_))
void sgemm_k(const float* __restrict__ A, const float* __restrict__ B,
             float* __restrict__ C, int M, int N, int K,
             const float* __restrict__ bias, int relu) {
    constexpr int NT = (BM_ / TM_) * (BN_ / TN_);
    __shared__ float As[BK_ * BM_];
    __shared__ float Bs[BK_ * BN_];
    int tid = threadIdx.x;
    int bm0 = blockIdx.y * BM_, bn0 = blockIdx.x * BN_;
    int tr = tid / (BN_ / TN_), tc = tid % (BN_ / TN_);
    float acc[TM_][TN_];
#pragma unroll
    for (int i = 0; i < TM_; i++)
#pragma unroll
        for (int j = 0; j < TN_; j++) acc[i][j] = 0.f;
    constexpr int AIT = (BM_ * BK_ / 4) / NT;
    constexpr int BIT = (BK_ * BN_ / 4) / NT;
    for (int k0 = 0; k0 < K; k0 += BK_) {
#pragma unroll
        for (int it = 0; it < AIT; it++) {
            int i = tid + it * NT;
            int ar = i / (BK_ / 4), ac = (i % (BK_ / 4)) * 4;
            float4 v = make_float4(0.f, 0.f, 0.f, 0.f);
            int gr = bm0 + ar;
            if (gr < M) v = *(const float4*)(A + (size_t)gr * K + k0 + ac);
            As[(ac + 0) * BM_ + ar] = v.x; As[(ac + 1) * BM_ + ar] = v.y;
            As[(ac + 2) * BM_ + ar] = v.z; As[(ac + 3) * BM_ + ar] = v.w;
        }
#pragma unroll
        for (int it = 0; it < BIT; it++) {
            int i = tid + it * NT;
            int br = i / (BN_ / 4), bc = (i % (BN_ / 4)) * 4;
            *(float4*)(Bs + br * BN_ + bc) = *(const float4*)(B + (size_t)(k0 + br) * N + bn0 + bc);
        }
        __syncthreads();
#pragma unroll
        for (int k = 0; k < BK_; k++) {
            float ra[TM_], rb[TN_];
#pragma unroll
            for (int i = 0; i < TM_; i++) ra[i] = As[k * BM_ + tr * TM_ + i];
#pragma unroll
            for (int j = 0; j < TN_; j++) rb[j] = Bs[k * BN_ + tc * TN_ + j];
#pragma unroll
            for (int i = 0; i < TM_; i++)
#pragma unroll
                for (int j = 0; j < TN_; j++) acc[i][j] += ra[i] * rb[j];
        }
        __syncthreads();
    }
#pragma unroll
    for (int i = 0; i < TM_; i++) {
        int row = bm0 + tr * TM_ + i;
        if (row >= M) continue;
#pragma unroll
        for (int j = 0; j < TN_; j += 4) {
            int col = bn0 + tc * TN_ + j;
            float4 v = make_float4(acc[i][j], acc[i][j + 1], acc[i][j + 2], acc[i][j + 3]);
            if (bias) {
                float4 bb = *(const float4*)(bias + col);
                v.x += bb.x; v.y += bb.y; v.z += bb.z; v.w += bb.w;
            }
            if (relu) {
                v.x = fmaxf(v.x, 0.f); v.y = fmaxf(v.y, 0.f);
                v.z = fmaxf(v.z, 0.f); v.w = fmaxf(v.w, 0.f);
            }
            *(float4*)(C + (size_t)row * N + col) = v;
        }
    }
}

// ---------------- pooling + output head ----------------
__global__ void pool_k(const int* __restrict__ batch) {
    int idx = blockIdx.x * blockDim.x + threadIdx.x;
    if (idx >= NN * 64) return;
    int n = idx >> 6, c = idx & 63;
    int bg = batch[n];
    uint2 vv = *(const uint2*)(g_gout + (size_t)n * DD + c * 4);
    float2 v0 = __half22float2(*(__half2*)&vv.x);
    float2 v1 = __half22float2(*(__half2*)&vv.y);
    float* d = g_pool + (size_t)bg * DD + c * 4;
    atomicAdd(d + 0, v0.x); atomicAdd(d + 1, v0.y);
    atomicAdd(d + 2, v1.x); atomicAdd(d + 3, v1.y);
}
__global__ void out_k(const float* __restrict__ W, const float* __restrict__ b,
                      float* __restrict__ out) {
    int g = blockIdx.x;
    int t = threadIdx.x;
    float4 z = *(const float4*)(g_z2 + (size_t)g * 512 + t * 4);
    float4 w = *(const float4*)(W + t * 4);
    float s = z.x * w.x + z.y * w.y + z.z * w.z + z.w * w.w;
#pragma unroll
    for (int o = 16; o > 0; o >>= 1) s += __shfl_down_sync(0xffffffffu, s, o);
    __shared__ float sm[4];
    if ((t & 31) == 0) sm[t >> 5] = s;
    __syncthreads();
    if (t == 0) out[g] = fmaxf(sm[0] + sm[1] + sm[2] + sm[3] + b[0], 0.f);
}

// ---------------- launch ----------------
extern "C" void kernel_launch(void* const* d_in, const int* in_sizes, int n_in,
                              void* d_out, int out_size) {
    const float* x      = (const float*)d_in[0];
    const int*   ei     = (const int*)d_in[1];
    const int*   et     = (const int*)d_in[2];
    const int*   batch  = (const int*)d_in[3];
    const float* encW   = (const float*)d_in[4];
    const float* encb   = (const float*)d_in[5];
    const float* preluA = (const float*)d_in[6];
    const float* relW   = (const float*)d_in[7];
    const float* rootW  = (const float*)d_in[8];
    const float* convb  = (const float*)d_in[9];
    const float* gpW1   = (const float*)d_in[10];
    const float* gpb1   = (const float*)d_in[11];
    const float* gpW2   = (const float*)d_in[12];
    const float* gpb2   = (const float*)d_in[13];
    const float* fcW1   = (const float*)d_in[14];
    const float* fcb1   = (const float*)d_in[15];
    const float* fcW2   = (const float*)d_in[16];
    const float* fcb2   = (const float*)d_in[17];
    const float* outW   = (const float*)d_in[18];
    const float* outb   = (const float*)d_in[19];
    float*       out    = (float*)d_out;

    float *p_pool, *p_z1, *p_z2;
    __half *p_Ah, *p_t1h, *p_gout, *p_Bgp;
    cudaGetSymbolAddress((void**)&p_pool, g_pool);
    cudaGetSymbolAddress((void**)&p_z1, g_z1);
    cudaGetSymbolAddress((void**)&p_z2, g_z2);
    cudaGetSymbolAddress((void**)&p_Ah, g_Ah);
    cudaGetSymbolAddress((void**)&p_t1h, g_t1h);
    cudaGetSymbolAddress((void**)&p_gout, g_gout);
    cudaGetSymbolAddress((void**)&p_Bgp, g_Bgp);

    // Ordered so mma_k is the 4th launch (ncu -s window catches it).
    encoder_k<<<NN, 256>>>(x, encW, encb);                                   // 1
    hist_k<<<(NE + 255) / 256, 256>>>(ei);                                   // 2
    convB_k<<<CONVB_BLKS + GP_BLKS + POOLZ_BLKS, 256>>>(relW, rootW, gpW1, gpW2); // 3
    mma_k<<<dim3(NC / BN2, MT), 256>>>(NN, 0);                               // 4 <- profile
    scan_k<<<1, 1024>>>();                                                   // 5
    scatter_k<<<(NE + 255) / 256, 256>>>(ei, et);                            // 6
    gather_k<<<NN, 64>>>(convb, preluA);                                     // 7 (layer 0)

    // layers 1..7
    for (int l = 1; l < NL; l++) {
        mma_k<<<dim3(NC / BN2, MT), 256>>>(NN, l);
        gather_k<<<NN, 64>>>(convb + (size_t)l * DD, preluA);
    }

    // graph head (fp16 tensor path)
    mma_head_k<<<dim3(2, MT), 256>>>(p_Ah, NN, p_Bgp, gpb1, 1, p_t1h);
    mma_head_k<<<dim3(2, MT), 256>>>(p_t1h, NN, p_Bgp + 65536, gpb2, 0, p_gout);

    pool_k<<<(NN * 64 + 255) / 256, 256>>>(batch);

    sgemm_k<64, 64, 16, 4, 4><<<dim3(1024 / 64, NG / 64), 256>>>(
        p_pool, fcW1, p_z1, NG, 1024, DD, fcb1, 1);
    sgemm_k<64, 64, 16, 4, 4><<<dim3(512 / 64, NG / 64), 256>>>(
        p_z1, fcW2, p_z2, NG, 512, 1024, fcb2, 1);
    out_k<<<NG, 128>>>(outW, outb, out);
}